// round 1
// baseline (speedup 1.0000x reference)
#include <cuda_runtime.h>
#include <cuda_bf16.h>
#include <math.h>

#define IN_CH 128
#define H 4
#define C 16
#define HC 64
#define MAXN 100000
#define MAXE 1600000
#define NEG_SLOPE 0.2f

// scratch (device globals — no allocation allowed)
__device__ float g_xp[MAXN * HC];      // 25.6 MB
__device__ float g_asrc[MAXN * H];
__device__ float g_adst[MAXN * H];
__device__ float g_m[MAXN * H];
__device__ float g_denom[MAXN * H];
__device__ float g_e[MAXE * H];        // 25.6 MB (logits, then exp)

__device__ __forceinline__ void atomicMaxF(float* addr, float v) {
    if (v >= 0.f) atomicMax((int*)addr, __float_as_int(v));
    else          atomicMin((unsigned int*)addr, __float_as_uint(v));
}

// ---------------------------------------------------------------------------
// K0: init m=-inf, denom=0, out=bias, edge_index->float copy
// ---------------------------------------------------------------------------
__global__ void k_init(float* __restrict__ out, float* __restrict__ out_ei,
                       const float* __restrict__ bias,
                       const int* __restrict__ edge_index,
                       int n, int e) {
    int total = n * HC;                 // largest range (6.4M)
    int twoE = 2 * e;
    if (twoE > total) total = twoE;
    for (int i = blockIdx.x * blockDim.x + threadIdx.x; i < total;
         i += gridDim.x * blockDim.x) {
        if (i < n * H) {
            g_m[i] = -INFINITY;
            g_denom[i] = 0.f;
        }
        if (i < n * HC) {
            out[i] = bias[i & (HC - 1)];
        }
        if (out_ei && i < twoE) {
            out_ei[i] = (float)edge_index[i];
        }
    }
}

// ---------------------------------------------------------------------------
// K1: xp = x @ W  (N x 128) @ (128 x 64), fused a_src/a_dst reduction
// block = 256 threads, 4 nodes per block
// ---------------------------------------------------------------------------
__global__ void k_gemm(const float* __restrict__ x, const float* __restrict__ W,
                       const float* __restrict__ att_src,
                       const float* __restrict__ att_dst, int n) {
    __shared__ float sW[IN_CH * HC];   // 32 KB
    __shared__ float sx[4 * IN_CH];    // 2 KB
    int tid = threadIdx.x;

    // load W
    #pragma unroll
    for (int i = 0; i < (IN_CH * HC) / 256; i++)
        sW[tid + i * 256] = W[tid + i * 256];

    int node0 = blockIdx.x * 4;
    // load 4 x rows
    #pragma unroll
    for (int i = 0; i < (4 * IN_CH) / 256; i++) {
        int idx = tid + i * 256;
        int nn = node0 + (idx >> 7);
        sx[idx] = (nn < n) ? x[(size_t)nn * IN_CH + (idx & 127)] : 0.f;
    }
    __syncthreads();

    int nl  = tid >> 6;      // local node 0..3
    int col = tid & 63;      // output col 0..63
    int node = node0 + nl;

    float acc = 0.f;
    const float* xr = &sx[nl * IN_CH];
    #pragma unroll 8
    for (int k = 0; k < IN_CH; k++)
        acc = fmaf(xr[k], sW[k * HC + col], acc);

    if (node < n) g_xp[(size_t)node * HC + col] = acc;

    int h = col >> 4;
    int c = col & 15;
    float s = acc * att_src[h * C + c];
    float d = acc * att_dst[h * C + c];
    #pragma unroll
    for (int off = 8; off >= 1; off >>= 1) {
        s += __shfl_down_sync(0xffffffffu, s, off, 16);
        d += __shfl_down_sync(0xffffffffu, d, off, 16);
    }
    if (c == 0 && node < n) {
        g_asrc[node * H + h] = s;
        g_adst[node * H + h] = d;
    }
}

// ---------------------------------------------------------------------------
// K2: per-edge logits (leaky relu) + segment max   (thread per edge)
// ---------------------------------------------------------------------------
__global__ void k_logits(const int* __restrict__ edge_index, int e) {
    int ei = blockIdx.x * blockDim.x + threadIdx.x;
    if (ei >= e) return;
    int src = edge_index[ei];
    int dst = edge_index[e + ei];
    float4 as = *(const float4*)&g_asrc[src * H];
    float4 ad = *(const float4*)&g_adst[dst * H];
    float4 l;
    l.x = as.x + ad.x; l.x = l.x > 0.f ? l.x : NEG_SLOPE * l.x;
    l.y = as.y + ad.y; l.y = l.y > 0.f ? l.y : NEG_SLOPE * l.y;
    l.z = as.z + ad.z; l.z = l.z > 0.f ? l.z : NEG_SLOPE * l.z;
    l.w = as.w + ad.w; l.w = l.w > 0.f ? l.w : NEG_SLOPE * l.w;
    *(float4*)&g_e[(size_t)ei * H] = l;
    float* mp = &g_m[dst * H];
    atomicMaxF(mp + 0, l.x);
    atomicMaxF(mp + 1, l.y);
    atomicMaxF(mp + 2, l.z);
    atomicMaxF(mp + 3, l.w);
}

// ---------------------------------------------------------------------------
// K3: e = exp(logit - m[dst]); denom[dst] += e
// ---------------------------------------------------------------------------
__global__ void k_exp(const int* __restrict__ edge_index, int e) {
    int ei = blockIdx.x * blockDim.x + threadIdx.x;
    if (ei >= e) return;
    int dst = edge_index[e + ei];
    float4 l = *(const float4*)&g_e[(size_t)ei * H];
    float4 m = *(const float4*)&g_m[dst * H];
    float4 ex;
    ex.x = __expf(l.x - m.x);
    ex.y = __expf(l.y - m.y);
    ex.z = __expf(l.z - m.z);
    ex.w = __expf(l.w - m.w);
    *(float4*)&g_e[(size_t)ei * H] = ex;
    float* dp = &g_denom[dst * H];
    atomicAdd(dp + 0, ex.x);
    atomicAdd(dp + 1, ex.y);
    atomicAdd(dp + 2, ex.z);
    atomicAdd(dp + 3, ex.w);
}

// ---------------------------------------------------------------------------
// K4: alpha = e/(denom+eps); out[dst] += xp[src]*alpha; write alpha
// 64 threads per edge
// ---------------------------------------------------------------------------
__global__ void k_scatter(const int* __restrict__ edge_index,
                          float* __restrict__ out,
                          float* __restrict__ out_alpha, int e) {
    long long gid = (long long)blockIdx.x * blockDim.x + threadIdx.x;
    long long totale = (long long)e * HC;
    if (gid >= totale) return;
    int ei = (int)(gid >> 6);
    int hc = (int)(gid & 63);
    int h = hc >> 4;
    int src = edge_index[ei];
    int dst = edge_index[e + ei];
    float ev  = g_e[(size_t)ei * H + h];
    float den = g_denom[dst * H + h];
    float alpha = ev / (den + 1e-16f);
    if (out_alpha && (hc & 15) == 0)
        out_alpha[(size_t)ei * H + h] = alpha;
    float val = g_xp[(size_t)src * HC + hc] * alpha;
    atomicAdd(&out[(size_t)dst * HC + hc], val);
}

extern "C" void kernel_launch(void* const* d_in, const int* in_sizes, int n_in,
                              void* d_out, int out_size) {
    const float* x       = (const float*)d_in[0];
    const float* W       = (const float*)d_in[1];
    const float* att_src = (const float*)d_in[2];
    const float* att_dst = (const float*)d_in[3];
    const float* bias    = (const float*)d_in[4];
    const int*   ei      = (const int*)d_in[5];

    int n = in_sizes[0] / IN_CH;
    int e = in_sizes[5] / 2;

    float* out = (float*)d_out;
    float* out_ei = nullptr;
    float* out_alpha = nullptr;
    if (out_size >= n * HC + 2 * e) out_ei = out + (size_t)n * HC;
    if (out_size >= n * HC + 2 * e + e * H)
        out_alpha = out + (size_t)n * HC + 2 * e;

    {   // K0
        int total = n * HC > 2 * e ? n * HC : 2 * e;
        int blocks = (total + 255) / 256;
        if (blocks > 8192) blocks = 8192;
        k_init<<<blocks, 256>>>(out, out_ei, bias, ei, n, e);
    }
    {   // K1
        int blocks = (n + 3) / 4;
        k_gemm<<<blocks, 256>>>(x, W, att_src, att_dst, n);
    }
    {   // K2
        k_logits<<<(e + 255) / 256, 256>>>(ei, e);
    }
    {   // K3
        k_exp<<<(e + 255) / 256, 256>>>(ei, e);
    }
    {   // K4
        long long total = (long long)e * HC;
        int blocks = (int)((total + 255) / 256);
        k_scatter<<<blocks, 256>>>(ei, out, out_alpha, e);
    }
}

// round 2
// speedup vs baseline: 3.2813x; 3.2813x over previous
#include <cuda_runtime.h>
#include <cuda_bf16.h>
#include <math.h>

#define IN_CH 128
#define H 4
#define C 16
#define HC 64
#define MAXN 100000
#define MAXE 1600000
#define NEG_SLOPE 0.2f

// scratch (device globals — allocation is forbidden)
__device__ __align__(16) float g_xp[MAXN * HC];      // 25.6 MB
__device__ __align__(16) float g_asrc[MAXN * H];
__device__ __align__(16) float g_adst[MAXN * H];
__device__ __align__(16) float g_denom[MAXN * H];
__device__ __align__(16) float g_e[MAXE * H];        // 25.6 MB

__device__ __forceinline__ void red_add_v4(float* p, float4 v) {
    asm volatile("red.global.add.v4.f32 [%0], {%1, %2, %3, %4};"
                 :: "l"(p), "f"(v.x), "f"(v.y), "f"(v.z), "f"(v.w) : "memory");
}

// ---------------------------------------------------------------------------
// K0: denom=0, out=bias, edge_index->float copy
// ---------------------------------------------------------------------------
__global__ void k_init(float* __restrict__ out, float* __restrict__ out_ei,
                       const float* __restrict__ bias,
                       const int* __restrict__ edge_index,
                       int n, int e) {
    int total = n * HC;
    int twoE = 2 * e;
    if (twoE > total) total = twoE;
    for (int i = blockIdx.x * blockDim.x + threadIdx.x; i < total;
         i += gridDim.x * blockDim.x) {
        if (i < n * H) g_denom[i] = 0.f;
        if (i < n * HC) out[i] = bias[i & (HC - 1)];
        if (out_ei && i < twoE) out_ei[i] = (float)edge_index[i];
    }
}

// ---------------------------------------------------------------------------
// K1: xp = x @ W, fused a_src/a_dst. 64 nodes/block, 4 nodes x 4 cols / thread
// ---------------------------------------------------------------------------
__global__ __launch_bounds__(256) void k_gemm(
        const float* __restrict__ x, const float* __restrict__ W,
        const float* __restrict__ att_src, const float* __restrict__ att_dst,
        int n) {
    __shared__ float4 sW4[IN_CH * 16];      // 32 KB, sW4[k*16+c] = W[k][4c..4c+3]
    __shared__ float  sx[64 * 129];         // 33 KB, padded stride vs bank conflicts
    int tid = threadIdx.x;
    int tx = tid & 15;       // col group: cols 4tx..4tx+3
    int ty = tid >> 4;       // node group: nodes 4ty..4ty+3
    int node0 = blockIdx.x * 64;

    const float4* W4 = (const float4*)W;
    #pragma unroll
    for (int i = 0; i < (IN_CH * 16) / 256; i++)
        sW4[tid + i * 256] = W4[tid + i * 256];

    #pragma unroll
    for (int i = 0; i < (64 * IN_CH) / 256; i++) {
        int idx = tid + i * 256;
        int nn = idx >> 7, k = idx & 127;
        int node = node0 + nn;
        sx[nn * 129 + k] = (node < n) ? x[(size_t)node * IN_CH + k] : 0.f;
    }
    __syncthreads();

    float4 acc[4];
    #pragma unroll
    for (int j = 0; j < 4; j++) acc[j] = make_float4(0.f, 0.f, 0.f, 0.f);

    #pragma unroll 4
    for (int k = 0; k < IN_CH; k++) {
        float4 w = sW4[k * 16 + tx];
        #pragma unroll
        for (int j = 0; j < 4; j++) {
            float xv = sx[(ty * 4 + j) * 129 + k];
            acc[j].x = fmaf(xv, w.x, acc[j].x);
            acc[j].y = fmaf(xv, w.y, acc[j].y);
            acc[j].z = fmaf(xv, w.z, acc[j].z);
            acc[j].w = fmaf(xv, w.w, acc[j].w);
        }
    }

    float4 a_s = ((const float4*)att_src)[tx];
    float4 a_d = ((const float4*)att_dst)[tx];
    #pragma unroll
    for (int j = 0; j < 4; j++) {
        int node = node0 + ty * 4 + j;
        if (node < n)
            ((float4*)g_xp)[(size_t)node * 16 + tx] = acc[j];
        float s = acc[j].x * a_s.x + acc[j].y * a_s.y +
                  acc[j].z * a_s.z + acc[j].w * a_s.w;
        float d = acc[j].x * a_d.x + acc[j].y * a_d.y +
                  acc[j].z * a_d.z + acc[j].w * a_d.w;
        s += __shfl_xor_sync(0xffffffffu, s, 1, 4);
        s += __shfl_xor_sync(0xffffffffu, s, 2, 4);
        d += __shfl_xor_sync(0xffffffffu, d, 1, 4);
        d += __shfl_xor_sync(0xffffffffu, d, 2, 4);
        if ((tx & 3) == 0 && node < n) {
            g_asrc[node * H + (tx >> 2)] = s;
            g_adst[node * H + (tx >> 2)] = d;
        }
    }
}

// ---------------------------------------------------------------------------
// K2: fused logit -> leakyrelu -> exp -> denom scatter (no max pass needed:
//     alpha = exp(l)/sum exp(l) is exactly the softmax; logits are O(4))
// ---------------------------------------------------------------------------
__global__ void k_exp(const int* __restrict__ edge_index, int e) {
    int ei = blockIdx.x * blockDim.x + threadIdx.x;
    if (ei >= e) return;
    int src = edge_index[ei];
    int dst = edge_index[e + ei];
    float4 as = ((const float4*)g_asrc)[src];
    float4 ad = ((const float4*)g_adst)[dst];
    float4 l;
    l.x = as.x + ad.x; l.x = l.x > 0.f ? l.x : NEG_SLOPE * l.x;
    l.y = as.y + ad.y; l.y = l.y > 0.f ? l.y : NEG_SLOPE * l.y;
    l.z = as.z + ad.z; l.z = l.z > 0.f ? l.z : NEG_SLOPE * l.z;
    l.w = as.w + ad.w; l.w = l.w > 0.f ? l.w : NEG_SLOPE * l.w;
    float4 ex;
    ex.x = __expf(l.x); ex.y = __expf(l.y);
    ex.z = __expf(l.z); ex.w = __expf(l.w);
    ((float4*)g_e)[ei] = ex;
    red_add_v4(&g_denom[dst * H], ex);
}

// ---------------------------------------------------------------------------
// K3: alpha = e/(denom+eps); out[dst] += xp[src]*alpha (float4 red);
//     16 threads per edge, each owns 4 contiguous cols
// ---------------------------------------------------------------------------
__global__ void k_scatter(const int* __restrict__ edge_index,
                          float* __restrict__ out,
                          float* __restrict__ out_alpha, int e) {
    long long gid = (long long)blockIdx.x * blockDim.x + threadIdx.x;
    long long total = (long long)e * 16;
    if (gid >= total) return;
    int ei = (int)(gid >> 4);
    int t  = (int)(gid & 15);     // col group
    int h  = t >> 2;              // head
    int src = edge_index[ei];
    int dst = edge_index[e + ei];
    float ev  = g_e[(size_t)ei * H + h];
    float den = g_denom[dst * H + h];
    float alpha = ev / (den + 1e-16f);
    if (out_alpha && (t & 3) == 0)
        out_alpha[(size_t)ei * H + h] = alpha;
    float4 v = ((const float4*)g_xp)[(size_t)src * 16 + t];
    v.x *= alpha; v.y *= alpha; v.z *= alpha; v.w *= alpha;
    red_add_v4(&out[(size_t)dst * HC + t * 4], v);
}

extern "C" void kernel_launch(void* const* d_in, const int* in_sizes, int n_in,
                              void* d_out, int out_size) {
    const float* x       = (const float*)d_in[0];
    const float* W       = (const float*)d_in[1];
    const float* att_src = (const float*)d_in[2];
    const float* att_dst = (const float*)d_in[3];
    const float* bias    = (const float*)d_in[4];
    const int*   ei      = (const int*)d_in[5];

    int n = in_sizes[0] / IN_CH;
    int e = in_sizes[5] / 2;

    float* out = (float*)d_out;
    float* out_ei = nullptr;
    float* out_alpha = nullptr;
    if (out_size >= n * HC + 2 * e) out_ei = out + (size_t)n * HC;
    if (out_size >= n * HC + 2 * e + e * H)
        out_alpha = out + (size_t)n * HC + 2 * e;

    {   // K0
        int total = n * HC > 2 * e ? n * HC : 2 * e;
        int blocks = (total + 255) / 256;
        if (blocks > 8192) blocks = 8192;
        k_init<<<blocks, 256>>>(out, out_ei, bias, ei, n, e);
    }
    {   // K1
        int blocks = (n + 63) / 64;
        k_gemm<<<blocks, 256>>>(x, W, att_src, att_dst, n);
    }
    {   // K2
        k_exp<<<(e + 255) / 256, 256>>>(ei, e);
    }
    {   // K3
        long long total = (long long)e * 16;
        int blocks = (int)((total + 255) / 256);
        k_scatter<<<blocks, 256>>>(ei, out, out_alpha, e);
    }
}